// round 6
// baseline (speedup 1.0000x reference)
#include <cuda_runtime.h>

#define M_DIM 1024
#define E_DIM 64
#define S_DIM 2048
#define GS_TOK 8192
#define GEMM_BLOCKS 128          // 64 tokens per block
#define FILL_BLOCKS 456          // one-wave persistent fill (128+456 = 584 <= 592 slots)
#define K1_BLOCKS (GEMM_BLOCKS + FILL_BLOCKS)

__device__ float g_proxy_partial[GEMM_BLOCKS * E_DIM];
__device__ int   g_expert[GS_TOK];
__device__ float g_gate[GS_TOK];
__device__ float g_group_loss[8];
__device__ unsigned int g_gemm_done;
__device__ unsigned int g_loss_cnt;
__device__ unsigned int g_scan_pass;

// ---------------------------------------------------------------------------
// K1: gating GEMM (f32x2 FFMA) + persistent zero-fill, all wave-1 resident.
// Every block triggers PDL completion at start so K2 launches ~immediately.
// ---------------------------------------------------------------------------
__global__ __launch_bounds__(256)
void k1_gemm_fill(const float* __restrict__ X, const float* __restrict__ W,
                  float* __restrict__ out, long long out_size)
{
    cudaTriggerProgrammaticLaunchCompletion();

    __shared__ float smem[4160];   // As[64][33]=2112 + Bs[32][64]=2048; L[64][65] overlays
    __shared__ float proxyS[E_DIM];

    int b = blockIdx.x;
    int tid = threadIdx.x;

    if (b < GEMM_BLOCKS) {
        float* As = smem;
        float* Bs = smem + 2112;
        int tx = tid & 15, ty = tid >> 4;
        if (tid < E_DIM) proxyS[tid] = 0.f;

        unsigned long long acc2[4][2];
        #pragma unroll
        for (int i = 0; i < 4; i++) { acc2[i][0] = 0ull; acc2[i][1] = 0ull; }

        int tbase = b * 64;
        const float* Xb = X + (long long)tbase * M_DIM;

        for (int kt = 0; kt < M_DIM; kt += 32) {
            #pragma unroll
            for (int j = 0; j < 2; j++) {
                int t  = (tid >> 3) + j * 32;
                int kq = tid & 7;
                float4 v = *(const float4*)(Xb + (long long)t * M_DIM + kt + kq * 4);
                float* dst = As + t * 33 + kq * 4;
                dst[0] = v.x; dst[1] = v.y; dst[2] = v.z; dst[3] = v.w;
            }
            #pragma unroll
            for (int j = 0; j < 2; j++) {
                int idx = tid + j * 256;
                int r = idx >> 4, c4 = idx & 15;
                ((float4*)Bs)[r * 16 + c4] = ((const float4*)(W + (long long)(kt + r) * E_DIM))[c4];
            }
            __syncthreads();
            #pragma unroll
            for (int kk = 0; kk < 32; kk++) {
                ulonglong2 bq = *((const ulonglong2*)(Bs + kk * 64) + tx);
                #pragma unroll
                for (int i = 0; i < 4; i++) {
                    float a = As[(ty * 4 + i) * 33 + kk];
                    unsigned long long ap;
                    asm("mov.b64 %0, {%1, %1};" : "=l"(ap) : "f"(a));
                    asm("fma.rn.f32x2 %0, %1, %2, %0;" : "+l"(acc2[i][0]) : "l"(ap), "l"(bq.x));
                    asm("fma.rn.f32x2 %0, %1, %2, %0;" : "+l"(acc2[i][1]) : "l"(ap), "l"(bq.y));
                }
            }
            __syncthreads();
        }

        float* L = smem;   // [64][65]
        #pragma unroll
        for (int i = 0; i < 4; i++) {
            float2 v0 = *reinterpret_cast<float2*>(&acc2[i][0]);
            float2 v1 = *reinterpret_cast<float2*>(&acc2[i][1]);
            float* row = L + (ty * 4 + i) * 65 + tx * 4;
            row[0] = v0.x; row[1] = v0.y; row[2] = v1.x; row[3] = v1.y;
        }
        __syncthreads();

        int w = tid >> 5, lane = tid & 31;
        float p0 = 0.f, p1 = 0.f;
        #pragma unroll
        for (int i = 0; i < 8; i++) {
            int row = w * 8 + i;
            float L0 = L[row * 65 + lane];
            float L1 = L[row * 65 + lane + 32];
            float v; int idx;
            if (L0 >= L1) { v = L0; idx = lane; } else { v = L1; idx = lane + 32; }
            #pragma unroll
            for (int off = 16; off; off >>= 1) {
                float ov = __shfl_xor_sync(0xffffffffu, v, off);
                int   oi = __shfl_xor_sync(0xffffffffu, idx, off);
                if (ov > v || (ov == v && oi < idx)) { v = ov; idx = oi; }
            }
            float e0 = expf(L0 - v);
            float e1 = expf(L1 - v);
            float s = e0 + e1;
            #pragma unroll
            for (int off = 16; off; off >>= 1)
                s += __shfl_xor_sync(0xffffffffu, s, off);
            float inv = 1.0f / s;
            p0 += e0 * inv;
            p1 += e1 * inv;
            if (lane == 0) {
                int t = tbase + row;
                g_expert[t] = idx;
                g_gate[t]   = inv;
            }
        }
        atomicAdd(&proxyS[lane], p0);
        atomicAdd(&proxyS[lane + 32], p1);
        __syncthreads();
        if (tid < E_DIM) g_proxy_partial[b * E_DIM + tid] = proxyS[tid];

        // release: signal GEMM completion
        __threadfence();
        __syncthreads();
        if (tid == 0) atomicAdd(&g_gemm_done, 1u);
    } else {
        // persistent contiguous-chunk zero fill with streaming stores
        long long n4  = out_size >> 2;
        long long fb  = b - GEMM_BLOCKS;
        long long per = n4 / FILL_BLOCKS;
        long long rem = n4 - per * FILL_BLOCKS;
        long long base = fb * per + (fb < rem ? fb : rem);
        if (fb < rem) per++;

        float4 z = make_float4(0.f, 0.f, 0.f, 0.f);
        float4* dst = (float4*)out + base;
        long long i = tid;
        for (; i + 768 < per; i += 1024) {
            __stcs(dst + i,       z);
            __stcs(dst + i + 256, z);
            __stcs(dst + i + 512, z);
            __stcs(dst + i + 768, z);
        }
        for (; i < per; i += 256) __stcs(dst + i, z);

        if (fb == 0) {   // scalar tail incl. aux slot (k2 overwrites aux post-sync)
            for (long long t = n4 * 4 + tid; t < out_size; t += 256)
                out[t] = 0.f;
        }
    }
}

// ---------------------------------------------------------------------------
// K2 (PDL secondary): scan + aux hidden under K1's fill; scatter after
// cudaGridDependencySynchronize. grid = G blocks x 256 threads.
// ---------------------------------------------------------------------------
__global__ __launch_bounds__(256)
void k2_scan_scatter(float* __restrict__ out, long long half, int C,
                     long long aux_idx, float aux_scale, int G)
{
    __shared__ int hist[64 * E_DIM];
    __shared__ unsigned char rank8[S_DIM];
    __shared__ unsigned char ex8[S_DIM];
    __shared__ float redS[E_DIM];
    __shared__ int   eposS[S_DIM];
    __shared__ float gateS[S_DIM];
    __shared__ float auxS;

    int g = blockIdx.x;
    int tid = threadIdx.x;
    int lane = tid & 31;
    unsigned lt = (1u << lane) - 1u;

    // wait for all GEMM blocks of K1 (fires ~40us into K1's ~140us runtime)
    if (tid == 0)
        while (*(volatile unsigned int*)&g_gemm_done < GEMM_BLOCKS) __nanosleep(64);
    __syncthreads();
    __threadfence();

    // scan-pass handshake: last block through resets counters for next replay
    if (tid == 0) {
        unsigned p = atomicAdd(&g_scan_pass, 1u);
        if (p == (unsigned)G - 1) { g_scan_pass = 0; g_gemm_done = 0; }
    }

    for (int i = tid; i < 64 * E_DIM; i += 256) hist[i] = 0;
    __syncthreads();

    // per-32-token-chunk histogram + in-chunk rank via match_any
    #pragma unroll
    for (int i = 0; i < 8; i++) {
        int s = i * 256 + tid;
        int e = g_expert[g * S_DIM + s];
        unsigned m = __match_any_sync(0xffffffffu, e);
        int r = __popc(m & lt);
        rank8[s] = (unsigned char)r;
        ex8[s]   = (unsigned char)e;
        if (r == 0) hist[(s >> 5) * E_DIM + e] = __popc(m);
    }
    __syncthreads();

    // exclusive prefix over 64 chunks + per-group aux term
    if (tid < E_DIM) {
        int run = 0;
        for (int c = 0; c < 64; c++) {
            int v = hist[c * E_DIM + tid];
            hist[c * E_DIM + tid] = run;
            run += v;
        }
        float proxy = 0.f;
        for (int bb = 0; bb < GEMM_BLOCKS / 4; bb++)
            proxy += g_proxy_partial[(g * (GEMM_BLOCKS / 4) + bb) * E_DIM + tid];
        const float invden = 1.0f / (2048.0f * 1.000001f);
        redS[tid] = (proxy * invden) * ((float)run * invden);
    }
    __syncthreads();
    if (tid < 32) {
        float v = redS[tid] + redS[tid + 32];
        #pragma unroll
        for (int off = 16; off; off >>= 1)
            v += __shfl_xor_sync(0xffffffffu, v, off);
        if (tid == 0) {
            g_group_loss[g] = v;
            __threadfence();
            atomicAdd(&g_loss_cnt, 1u);
        }
    }

    // stage packed (expert*C+pos) and gate in smem (still hidden under fill)
    #pragma unroll
    for (int i = 0; i < 8; i++) {
        int s = i * 256 + tid;
        int e = ex8[s];
        int pos = hist[(s >> 5) * E_DIM + e] + (int)rank8[s];
        eposS[s] = (pos < C) ? (e * C + pos) : -1;
        gateS[s] = g_gate[g * S_DIM + s];
    }

    // block 0 finalizes aux (deterministic order), resets g_loss_cnt
    if (g == 0 && tid == 0) {
        while (*(volatile unsigned int*)&g_loss_cnt < (unsigned)G) __nanosleep(64);
        __threadfence();
        float a = 0.f;
        for (int gg = 0; gg < G; gg++) a += g_group_loss[gg];
        auxS = a * aux_scale;
        g_loss_cnt = 0;
    }
    __syncthreads();

    // wait for K1 (fill) to fully complete, then scatter pure stores
    cudaGridDependencySynchronize();

    long long EC = (long long)E_DIM * C;
    #pragma unroll
    for (int i = 0; i < 8; i++) {
        int s = i * 256 + tid;
        int ep = eposS[s];
        if (ep >= 0) {
            long long idx = (long long)(g * S_DIM + s) * EC + ep;
            out[idx]        = gateS[s];
            out[half + idx] = 1.0f;
        }
    }
    if (g == 0 && tid == 0) out[aux_idx] = auxS;
}

extern "C" void kernel_launch(void* const* d_in, const int* in_sizes, int n_in,
                              void* d_out, int out_size)
{
    const float* X = (const float*)d_in[0];
    const float* W = (const float*)d_in[1];
    float* out = (float*)d_out;

    long long osz  = (long long)out_size;
    long long half = (osz - 1) / 2;
    int GS = in_sizes[0] / M_DIM;                    // 8192
    int C  = (int)(half / ((long long)GS * E_DIM));  // 160
    int G  = GS / S_DIM;                             // 4
    float aux_scale = (float)((double)E_DIM * E_DIM * 0.01 / ((double)G * E_DIM));

    k1_gemm_fill<<<K1_BLOCKS, 256>>>(X, W, out, osz);

    // PDL secondary launch: may start while k1 is still filling
    cudaLaunchConfig_t cfg = {};
    cfg.gridDim  = dim3((unsigned)G, 1, 1);
    cfg.blockDim = dim3(256, 1, 1);
    cfg.dynamicSmemBytes = 0;
    cfg.stream = 0;
    cudaLaunchAttribute attr[1];
    attr[0].id = cudaLaunchAttributeProgrammaticStreamSerialization;
    attr[0].val.programmaticStreamSerializationAllowed = 1;
    cfg.attrs = attr;
    cfg.numAttrs = 1;
    cudaLaunchKernelEx(&cfg, k2_scan_scatter, out, half, C, osz - 1, aux_scale, G);
}

// round 7
// speedup vs baseline: 1.0164x; 1.0164x over previous
#include <cuda_runtime.h>

#define M_DIM 1024
#define E_DIM 64
#define S_DIM 2048
#define GS_TOK 8192
#define GEMM_BLOCKS 128      // 64 tokens per block
#define FILL_BLOCKS 2048

__device__ float g_proxy_partial[GEMM_BLOCKS * E_DIM];
__device__ int   g_expert[GS_TOK];
__device__ float g_gate[GS_TOK];
__device__ unsigned int g_gemm_done;
__device__ unsigned int g_fill_done;

// ---------------------------------------------------------------------------
// K1: identical to R2's best (GEMM + fill), plus completion counters.
// ---------------------------------------------------------------------------
__global__ __launch_bounds__(256)
void k1_gemm_fill(const float* __restrict__ X, const float* __restrict__ W,
                  float* __restrict__ out, long long out_size)
{
    __shared__ float smem[4160];   // As[64][33]=2112 + Bs[32][64]=2048; L[64][65] overlays
    __shared__ float proxyS[E_DIM];

    int b = blockIdx.x;
    int tid = threadIdx.x;

    if (b < GEMM_BLOCKS) {
        float* As = smem;
        float* Bs = smem + 2112;
        int tx = tid & 15, ty = tid >> 4;
        if (tid < E_DIM) proxyS[tid] = 0.f;

        unsigned long long acc2[4][2];
        #pragma unroll
        for (int i = 0; i < 4; i++) { acc2[i][0] = 0ull; acc2[i][1] = 0ull; }

        int tbase = b * 64;
        const float* Xb = X + (long long)tbase * M_DIM;

        for (int kt = 0; kt < M_DIM; kt += 32) {
            #pragma unroll
            for (int j = 0; j < 2; j++) {
                int t  = (tid >> 3) + j * 32;
                int kq = tid & 7;
                float4 v = *(const float4*)(Xb + (long long)t * M_DIM + kt + kq * 4);
                float* dst = As + t * 33 + kq * 4;
                dst[0] = v.x; dst[1] = v.y; dst[2] = v.z; dst[3] = v.w;
            }
            #pragma unroll
            for (int j = 0; j < 2; j++) {
                int idx = tid + j * 256;
                int r = idx >> 4, c4 = idx & 15;
                ((float4*)Bs)[r * 16 + c4] = ((const float4*)(W + (long long)(kt + r) * E_DIM))[c4];
            }
            __syncthreads();
            #pragma unroll
            for (int kk = 0; kk < 32; kk++) {
                ulonglong2 bq = *((const ulonglong2*)(Bs + kk * 64) + tx);
                #pragma unroll
                for (int i = 0; i < 4; i++) {
                    float a = As[(ty * 4 + i) * 33 + kk];
                    unsigned long long ap;
                    asm("mov.b64 %0, {%1, %1};" : "=l"(ap) : "f"(a));
                    asm("fma.rn.f32x2 %0, %1, %2, %0;" : "+l"(acc2[i][0]) : "l"(ap), "l"(bq.x));
                    asm("fma.rn.f32x2 %0, %1, %2, %0;" : "+l"(acc2[i][1]) : "l"(ap), "l"(bq.y));
                }
            }
            __syncthreads();
        }

        float* L = smem;   // [64][65]
        #pragma unroll
        for (int i = 0; i < 4; i++) {
            float2 v0 = *reinterpret_cast<float2*>(&acc2[i][0]);
            float2 v1 = *reinterpret_cast<float2*>(&acc2[i][1]);
            float* row = L + (ty * 4 + i) * 65 + tx * 4;
            row[0] = v0.x; row[1] = v0.y; row[2] = v1.x; row[3] = v1.y;
        }
        __syncthreads();

        int w = tid >> 5, lane = tid & 31;
        float p0 = 0.f, p1 = 0.f;
        #pragma unroll
        for (int i = 0; i < 8; i++) {
            int row = w * 8 + i;
            float L0 = L[row * 65 + lane];
            float L1 = L[row * 65 + lane + 32];
            float v; int idx;
            if (L0 >= L1) { v = L0; idx = lane; } else { v = L1; idx = lane + 32; }
            #pragma unroll
            for (int off = 16; off; off >>= 1) {
                float ov = __shfl_xor_sync(0xffffffffu, v, off);
                int   oi = __shfl_xor_sync(0xffffffffu, idx, off);
                if (ov > v || (ov == v && oi < idx)) { v = ov; idx = oi; }
            }
            float e0 = expf(L0 - v);
            float e1 = expf(L1 - v);
            float s = e0 + e1;
            #pragma unroll
            for (int off = 16; off; off >>= 1)
                s += __shfl_xor_sync(0xffffffffu, s, off);
            float inv = 1.0f / s;
            p0 += e0 * inv;
            p1 += e1 * inv;
            if (lane == 0) {
                int t = tbase + row;
                g_expert[t] = idx;
                g_gate[t]   = inv;
            }
        }
        atomicAdd(&proxyS[lane], p0);
        atomicAdd(&proxyS[lane + 32], p1);
        __syncthreads();
        if (tid < E_DIM) g_proxy_partial[b * E_DIM + tid] = proxyS[tid];

        __threadfence();
        __syncthreads();
        if (tid == 0) atomicAdd(&g_gemm_done, 1u);
    } else {
        long long n4  = out_size >> 2;
        long long fb  = b - GEMM_BLOCKS;
        long long per = n4 / FILL_BLOCKS;
        long long rem = n4 - per * FILL_BLOCKS;
        long long base = fb * per + (fb < rem ? fb : rem);
        if (fb < rem) per++;

        float4 z = make_float4(0.f, 0.f, 0.f, 0.f);
        float4* dst = (float4*)out + base;
        long long i = tid;
        for (; i + 768 < per; i += 1024) {
            __stcs(dst + i,       z);
            __stcs(dst + i + 256, z);
            __stcs(dst + i + 512, z);
            __stcs(dst + i + 768, z);
        }
        for (; i < per; i += 256) __stcs(dst + i, z);

        if (fb == 0) {   // scalar tail incl. aux slot (k2 overwrites aux later)
            for (long long t = n4 * 4 + tid; t < out_size; t += 256)
                out[t] = 0.f;
        }

        __threadfence();
        __syncthreads();
        if (tid == 0) atomicAdd(&g_fill_done, 1u);
    }
}

// ---------------------------------------------------------------------------
// K2 (concurrent stream): single block, 1024 threads.
// Scan + aux hidden under k1's fill; scatter after fill completes.
// ---------------------------------------------------------------------------
__global__ __launch_bounds__(1024)
void k2_scan_scatter(float* __restrict__ out, long long half, int C,
                     long long aux_idx, float aux_scale)
{
    __shared__ int hist[64 * E_DIM];
    __shared__ unsigned char rank8[S_DIM];
    __shared__ unsigned char ex8[S_DIM];
    __shared__ float redS[E_DIM];
    __shared__ float auxS;

    int tid = threadIdx.x;
    int lane = tid & 31;
    unsigned lt = (1u << lane) - 1u;
    const int G = GS_TOK / S_DIM;

    // wait for all GEMM blocks (ready ~40us into k1; we are hidden until then)
    if (tid == 0)
        while (*(volatile unsigned int*)&g_gemm_done < GEMM_BLOCKS) __nanosleep(128);
    __syncthreads();
    __threadfence();

    int   eposR[8];
    float gateR[8];
    float auxAcc = 0.f;

    for (int g = 0; g < G; g++) {
        for (int i = tid; i < 64 * E_DIM; i += 1024) hist[i] = 0;
        __syncthreads();

        #pragma unroll
        for (int h = 0; h < 2; h++) {
            int s = h * 1024 + tid;
            int e = g_expert[g * S_DIM + s];
            unsigned m = __match_any_sync(0xffffffffu, e);
            int r = __popc(m & lt);
            rank8[s] = (unsigned char)r;
            ex8[s]   = (unsigned char)e;
            if (r == 0) hist[(s >> 5) * E_DIM + e] = __popc(m);
        }
        __syncthreads();

        if (tid < E_DIM) {
            int run = 0;
            for (int c = 0; c < 64; c++) {
                int v = hist[c * E_DIM + tid];
                hist[c * E_DIM + tid] = run;
                run += v;
            }
            float proxy = 0.f;
            for (int bb = 0; bb < GEMM_BLOCKS / 4; bb++)
                proxy += g_proxy_partial[(g * (GEMM_BLOCKS / 4) + bb) * E_DIM + tid];
            const float invden = 1.0f / (2048.0f * 1.000001f);
            auxAcc += (proxy * invden) * ((float)run * invden);
        }
        __syncthreads();

        #pragma unroll
        for (int h = 0; h < 2; h++) {
            int s = h * 1024 + tid;
            int e = ex8[s];
            int pos = hist[(s >> 5) * E_DIM + e] + (int)rank8[s];
            eposR[g * 2 + h] = (pos < C) ? (e * C + pos) : -1;
            gateR[g * 2 + h] = g_gate[g * S_DIM + s];
        }
        __syncthreads();
    }

    if (tid < E_DIM) redS[tid] = auxAcc;
    __syncthreads();
    if (tid < 32) {
        float v = redS[tid] + redS[tid + 32];
        #pragma unroll
        for (int off = 16; off; off >>= 1)
            v += __shfl_xor_sync(0xffffffffu, v, off);
        if (tid == 0) auxS = v * aux_scale;
    }

    // wait for the fill to fully complete, then scatter over the zeroed output
    if (tid == 0)
        while (*(volatile unsigned int*)&g_fill_done < FILL_BLOCKS) __nanosleep(256);
    __syncthreads();
    __threadfence();

    long long EC = (long long)E_DIM * C;
    #pragma unroll
    for (int g = 0; g < 4; g++) {
        #pragma unroll
        for (int h = 0; h < 2; h++) {
            int ep = eposR[g * 2 + h];
            if (ep >= 0) {
                long long t = (long long)g * S_DIM + h * 1024 + tid;
                long long idx = t * EC + ep;
                out[idx]        = gateR[g * 2 + h];
                out[half + idx] = 1.0f;
            }
        }
    }
    if (tid == 0) out[aux_idx] = auxS;

    __syncthreads();
    if (tid == 0) {          // last actor in the graph: reset for next replay
        g_gemm_done = 0;
        g_fill_done = 0;
        __threadfence();
    }
}

extern "C" void kernel_launch(void* const* d_in, const int* in_sizes, int n_in,
                              void* d_out, int out_size)
{
    const float* X = (const float*)d_in[0];
    const float* W = (const float*)d_in[1];
    float* out = (float*)d_out;

    long long osz  = (long long)out_size;
    long long half = (osz - 1) / 2;
    int GS = in_sizes[0] / M_DIM;                    // 8192
    int C  = (int)(half / ((long long)GS * E_DIM));  // 160
    int G  = GS / S_DIM;                             // 4
    float aux_scale = (float)((double)E_DIM * E_DIM * 0.01 / ((double)G * E_DIM));

    static cudaStream_t s2 = nullptr;
    static cudaEvent_t evFork = nullptr, evJoin = nullptr;
    if (s2 == nullptr) {
        cudaStreamCreateWithFlags(&s2, cudaStreamNonBlocking);
        cudaEventCreateWithFlags(&evFork, cudaEventDisableTiming);
        cudaEventCreateWithFlags(&evJoin, cudaEventDisableTiming);
    }

    // fork: k2 runs concurrently with k1 on a second stream
    cudaEventRecord(evFork, 0);
    cudaStreamWaitEvent(s2, evFork, 0);

    k1_gemm_fill<<<GEMM_BLOCKS + FILL_BLOCKS, 256>>>(X, W, out, osz);
    k2_scan_scatter<<<1, 1024, 0, s2>>>(out, half, C, osz - 1, aux_scale);

    // join: main stream waits for k2 (k1 already ordered on main stream)
    cudaEventRecord(evJoin, s2);
    cudaStreamWaitEvent(0, evJoin, 0);
}

// round 8
// speedup vs baseline: 1.1215x; 1.1034x over previous
#include <cuda_runtime.h>

#define M_DIM 1024
#define E_DIM 64
#define S_DIM 2048
#define GS_TOK 8192
#define GEMM_BLOCKS 128      // 64 tokens per block
#define FILL_BLOCKS 2048

__device__ float g_proxy_partial[GEMM_BLOCKS * E_DIM];
__device__ int   g_expert[GS_TOK];
__device__ float g_gate[GS_TOK];
__device__ float g_group_loss[8];
__device__ unsigned int g_loss_cnt;

// ---------------------------------------------------------------------------
// K1: EXACT R2 best — fused zero-fill + gating GEMM (f32x2 FFMA) + softmax
// ---------------------------------------------------------------------------
__global__ __launch_bounds__(256)
void k1_gemm_fill(const float* __restrict__ X, const float* __restrict__ W,
                  float* __restrict__ out, long long out_size)
{
    __shared__ float smem[4160];   // As[64][33]=2112 + Bs[32][64]=2048; L[64][65] overlays
    __shared__ float proxyS[E_DIM];

    int b = blockIdx.x;
    if (b < GEMM_BLOCKS) {
        if (b == 0 && threadIdx.x == 0) g_loss_cnt = 0;   // reset for this replay

        float* As = smem;
        float* Bs = smem + 2112;
        int tid = threadIdx.x;
        int tx = tid & 15, ty = tid >> 4;
        if (tid < E_DIM) proxyS[tid] = 0.f;

        unsigned long long acc2[4][2];
        #pragma unroll
        for (int i = 0; i < 4; i++) { acc2[i][0] = 0ull; acc2[i][1] = 0ull; }

        int tbase = b * 64;
        const float* Xb = X + (long long)tbase * M_DIM;

        for (int kt = 0; kt < M_DIM; kt += 32) {
            #pragma unroll
            for (int j = 0; j < 2; j++) {
                int t  = (tid >> 3) + j * 32;
                int kq = tid & 7;
                float4 v = *(const float4*)(Xb + (long long)t * M_DIM + kt + kq * 4);
                float* dst = As + t * 33 + kq * 4;
                dst[0] = v.x; dst[1] = v.y; dst[2] = v.z; dst[3] = v.w;
            }
            #pragma unroll
            for (int j = 0; j < 2; j++) {
                int idx = tid + j * 256;
                int r = idx >> 4, c4 = idx & 15;
                ((float4*)Bs)[r * 16 + c4] = ((const float4*)(W + (long long)(kt + r) * E_DIM))[c4];
            }
            __syncthreads();
            #pragma unroll
            for (int kk = 0; kk < 32; kk++) {
                ulonglong2 bq = *((const ulonglong2*)(Bs + kk * 64) + tx);
                #pragma unroll
                for (int i = 0; i < 4; i++) {
                    float a = As[(ty * 4 + i) * 33 + kk];
                    unsigned long long ap;
                    asm("mov.b64 %0, {%1, %1};" : "=l"(ap) : "f"(a));
                    asm("fma.rn.f32x2 %0, %1, %2, %0;" : "+l"(acc2[i][0]) : "l"(ap), "l"(bq.x));
                    asm("fma.rn.f32x2 %0, %1, %2, %0;" : "+l"(acc2[i][1]) : "l"(ap), "l"(bq.y));
                }
            }
            __syncthreads();
        }

        float* L = smem;
        #pragma unroll
        for (int i = 0; i < 4; i++) {
            float2 v0 = *reinterpret_cast<float2*>(&acc2[i][0]);
            float2 v1 = *reinterpret_cast<float2*>(&acc2[i][1]);
            float* row = L + (ty * 4 + i) * 65 + tx * 4;
            row[0] = v0.x; row[1] = v0.y; row[2] = v1.x; row[3] = v1.y;
        }
        __syncthreads();

        int w = tid >> 5, lane = tid & 31;
        float p0 = 0.f, p1 = 0.f;
        #pragma unroll
        for (int i = 0; i < 8; i++) {
            int row = w * 8 + i;
            float L0 = L[row * 65 + lane];
            float L1 = L[row * 65 + lane + 32];
            float v; int idx;
            if (L0 >= L1) { v = L0; idx = lane; } else { v = L1; idx = lane + 32; }
            #pragma unroll
            for (int off = 16; off; off >>= 1) {
                float ov = __shfl_xor_sync(0xffffffffu, v, off);
                int   oi = __shfl_xor_sync(0xffffffffu, idx, off);
                if (ov > v || (ov == v && oi < idx)) { v = ov; idx = oi; }
            }
            float e0 = expf(L0 - v);
            float e1 = expf(L1 - v);
            float s = e0 + e1;
            #pragma unroll
            for (int off = 16; off; off >>= 1)
                s += __shfl_xor_sync(0xffffffffu, s, off);
            float inv = 1.0f / s;
            p0 += e0 * inv;
            p1 += e1 * inv;
            if (lane == 0) {
                int t = tbase + row;
                g_expert[t] = idx;
                g_gate[t]   = inv;
            }
        }
        atomicAdd(&proxyS[lane], p0);
        atomicAdd(&proxyS[lane + 32], p1);
        __syncthreads();
        if (tid < E_DIM) g_proxy_partial[b * E_DIM + tid] = proxyS[tid];
    } else {
        long long n4  = out_size >> 2;
        long long fb  = b - GEMM_BLOCKS;
        long long per = n4 / FILL_BLOCKS;
        long long rem = n4 - per * FILL_BLOCKS;
        long long base = fb * per + (fb < rem ? fb : rem);
        if (fb < rem) per++;

        float4 z = make_float4(0.f, 0.f, 0.f, 0.f);
        float4* dst = (float4*)out + base;
        long long i = threadIdx.x;
        for (; i + 768 < per; i += 1024) {
            __stcs(dst + i,       z);
            __stcs(dst + i + 256, z);
            __stcs(dst + i + 512, z);
            __stcs(dst + i + 768, z);
        }
        for (; i < per; i += 256) __stcs(dst + i, z);

        if (fb == 0) {
            for (long long t = n4 * 4 + threadIdx.x; t < out_size; t += 256)
                out[t] = 0.f;
        }
    }
}

// ---------------------------------------------------------------------------
// K2: scan (Kogge-Stone prefix) + scatter first + aux loss last
// grid = G blocks x 1024 threads
// ---------------------------------------------------------------------------
__global__ __launch_bounds__(1024)
void k2_scan_scatter(float* __restrict__ out, long long half, int C,
                     long long aux_idx, float aux_scale, int G)
{
    __shared__ int hist[64 * E_DIM];     // [chunk][expert], becomes inclusive prefix
    __shared__ float redS[E_DIM];

    int g = blockIdx.x;
    int tid = threadIdx.x;
    int lane = tid & 31;
    unsigned lt = (1u << lane) - 1u;

    // prefetch everything this thread needs from global (long-latency first)
    int   e0 = g_expert[g * S_DIM + tid];
    int   e1 = g_expert[g * S_DIM + 1024 + tid];
    float gate0 = g_gate[g * S_DIM + tid];
    float gate1 = g_gate[g * S_DIM + 1024 + tid];
    float proxy = 0.f;
    if (tid < E_DIM) {
        #pragma unroll 4
        for (int bb = 0; bb < GEMM_BLOCKS / 4; bb++)
            proxy += g_proxy_partial[(g * (GEMM_BLOCKS / 4) + bb) * E_DIM + tid];
    }

    for (int i = tid; i < 64 * E_DIM; i += 1024) hist[i] = 0;
    __syncthreads();

    // per-32-token-chunk histogram + in-warp ranks (kept in registers)
    unsigned m0 = __match_any_sync(0xffffffffu, e0);
    int r0 = __popc(m0 & lt);
    if (r0 == 0) hist[(tid >> 5) * E_DIM + e0] = __popc(m0);
    unsigned m1 = __match_any_sync(0xffffffffu, e1);
    int r1 = __popc(m1 & lt);
    if (r1 == 0) hist[((1024 + tid) >> 5) * E_DIM + e1] = __popc(m1);
    __syncthreads();

    // Kogge-Stone inclusive scan along the chunk axis (64 chunks x 64 experts)
    #pragma unroll
    for (int d = 1; d < 64; d <<= 1) {
        int v[4];
        #pragma unroll
        for (int j = 0; j < 4; j++) {
            int idx = tid + j * 1024;
            int c = idx >> 6;                    // chunk
            v[j] = hist[idx] + (c >= d ? hist[idx - (d << 6)] : 0);
        }
        __syncthreads();
        #pragma unroll
        for (int j = 0; j < 4; j++) hist[tid + j * 1024] = v[j];
        __syncthreads();
    }

    // positions (exclusive = inclusive[c-1]) + capacity drop + scatter now
    long long EC = (long long)E_DIM * C;
    {
        int c = tid >> 5;
        int pos = (c ? hist[(c - 1) * E_DIM + e0] : 0) + r0;
        if (pos < C) {
            long long t = (long long)g * S_DIM + tid;
            long long idx = t * EC + e0 * C + pos;
            out[idx]        = gate0;
            out[half + idx] = 1.0f;
        }
    }
    {
        int s = 1024 + tid;
        int c = s >> 5;
        int pos = (c ? hist[(c - 1) * E_DIM + e1] : 0) + r1;
        if (pos < C) {
            long long t = (long long)g * S_DIM + s;
            long long idx = t * EC + e1 * C + pos;
            out[idx]        = gate1;
            out[half + idx] = 1.0f;
        }
    }

    // aux loss last (doesn't delay the scatter stores)
    if (tid < E_DIM) {
        int run = hist[63 * E_DIM + tid];     // total tokens for this expert
        const float invden = 1.0f / (2048.0f * 1.000001f);
        redS[tid] = (proxy * invden) * ((float)run * invden);
    }
    __syncthreads();
    if (tid < 32) {
        float v = redS[tid] + redS[tid + 32];
        #pragma unroll
        for (int off = 16; off; off >>= 1)
            v += __shfl_xor_sync(0xffffffffu, v, off);
        if (tid == 0) {
            g_group_loss[g] = v;
            __threadfence();
            atomicAdd(&g_loss_cnt, 1u);
        }
    }
    if (g == 0 && tid == 0) {
        while (atomicAdd(&g_loss_cnt, 0u) < (unsigned)G) { }
        float a = 0.f;
        for (int gg = 0; gg < G; gg++) a += g_group_loss[gg];
        out[aux_idx] = a * aux_scale;
    }
}

extern "C" void kernel_launch(void* const* d_in, const int* in_sizes, int n_in,
                              void* d_out, int out_size)
{
    const float* X = (const float*)d_in[0];
    const float* W = (const float*)d_in[1];
    float* out = (float*)d_out;

    long long osz  = (long long)out_size;
    long long half = (osz - 1) / 2;
    int GS = in_sizes[0] / M_DIM;                    // 8192
    int C  = (int)(half / ((long long)GS * E_DIM));  // 160
    int G  = GS / S_DIM;                             // 4
    float aux_scale = (float)((double)E_DIM * E_DIM * 0.01 / ((double)G * E_DIM));

    k1_gemm_fill<<<GEMM_BLOCKS + FILL_BLOCKS, 256>>>(X, W, out, osz);
    k2_scan_scatter<<<G, 1024>>>(out, half, C, osz - 1, aux_scale, G);
}